// round 9
// baseline (speedup 1.0000x reference)
#include <cuda_runtime.h>
#include <math.h>
#include <stdint.h>

#define N_NODES 50000
#define N_EDGES 400000
#define EPB 64   // edges per block in k_edge

// Scale constants
#define INV_S64  0.125f                  // 1/sqrt(64)
#define INV_S32  0.17677669529663687f    // 1/sqrt(32)
#define INV_S10  0.31622776601683794f    // 1/sqrt(10)
#define INV_S96  0.10206207261596575f    // 1/sqrt(96)
#define INV_S3   0.57735026918962576f    // 1/sqrt(3)

// ---------------- scratch (device globals; no allocation allowed) ----------
__device__ __align__(16) float d_hs [N_NODES * 64];
__device__ __align__(16) float d_hv [N_NODES * 96];
__device__ __align__(16) float d_scs[N_NODES * 96];
__device__ __align__(16) float d_scv[N_NODES * 96];
__device__ __align__(16) float d_Ms [N_NODES * 96];
__device__ __align__(16) float d_Mv [N_NODES * 288];
__device__ float d_deg[N_NODES];
__device__ __align__(16) float d_gs [N_NODES * 64];
__device__ __align__(16) float d_v1 [N_NODES * 96];
// fragment-packed tf32 weight tables
__device__ float d_w2f  [2][12288];  // edge Wfc2 (K=64, NT=24)
__device__ float d_preS [2][10240];  // lin1_s || sc_s   (K=64, NT=20/16)
__device__ float d_preV [2][2048];   // lin1_v || sc_v   (K=32, NT=8)
__device__ float d_postS[2][9984];   // lin2_s || alpha  (K=96, NT=13/9)
__device__ float d_postV[2][3072];   // lin2_v           (K=96, NT=4)

__device__ __forceinline__ float sigmoidf_(float x) { return 1.0f / (1.0f + __expf(-x)); }
__device__ __forceinline__ float siluf_(float x)    { return x / (1.0f + __expf(-x)); }

__device__ __forceinline__ float tf32r(float x) {
    uint32_t u;
    asm("cvt.rna.tf32.f32 %0, %1;" : "=r"(u) : "f"(x));
    return __uint_as_float(u);
}

__device__ __forceinline__ void mma_tf32(float c[4],
    uint32_t a0, uint32_t a1, uint32_t a2, uint32_t a3,
    uint32_t b0, uint32_t b1)
{
    asm volatile(
        "mma.sync.aligned.m16n8k8.row.col.f32.tf32.tf32.f32 "
        "{%0,%1,%2,%3},{%4,%5,%6,%7},{%8,%9},{%0,%1,%2,%3};"
        : "+f"(c[0]), "+f"(c[1]), "+f"(c[2]), "+f"(c[3])
        : "r"(a0), "r"(a1), "r"(a2), "r"(a3), "r"(b0), "r"(b1));
}

__device__ __forceinline__ void red4(float* p, float4 v) {
    atomicAdd(reinterpret_cast<float4*>(p), v);
}

// ---------------- degree ---------------------------------------------------
__global__ void k_deg_zero() {
    int i = blockIdx.x * blockDim.x + threadIdx.x;
    if (i < N_NODES) d_deg[i] = 0.0f;
}
__global__ void k_deg(const int* __restrict__ dst) {
    int i = blockIdx.x * blockDim.x + threadIdx.x;
    if (i < N_EDGES) atomicAdd(&d_deg[dst[i]], 1.0f);
}

// ---------------- weight packing -------------------------------------------
// Proven fragment order: idx = ((S*NT + T)*2 + half)*32 + lane,
// value = W[(8S + kc + 4*half)*ld + 8T + row], row=lane>>2, kc=lane&3.
__global__ void k_prep(const float* __restrict__ W2a, const float* __restrict__ W2b) {
    int t = blockIdx.x * 256 + threadIdx.x;
    if (t >= 24576) return;
    int lay = t / 12288, r = t % 12288;
    int S = r / 1536;
    int rem = r % 1536;
    int T = rem / 64;
    int rem2 = rem % 64;
    int half = rem2 >> 5, lane = rem2 & 31;
    int row = lane >> 2, kc = lane & 3;
    const float* W = lay ? W2b : W2a;
    d_w2f[lay][r] = tf32r(W[(8 * S + kc + 4 * half) * 192 + 8 * T + row]);
}

// Generic packer: cols [0,mcols) from Wm (ld=ldm), [mcols,mcols+ecols) from We, else 0.
__global__ void k_pack(int table, int layer,
                       const float* __restrict__ Wm, const float* __restrict__ We,
                       int K, int NT, int mcols, int ldm, int ecols, int lde)
{
    float* dst = (table == 0) ? d_preS[layer] :
                 (table == 1) ? d_preV[layer] :
                 (table == 2) ? d_postS[layer] : d_postV[layer];
    int total = (K / 8) * NT * 64;
    for (int t = blockIdx.x * blockDim.x + threadIdx.x; t < total;
         t += gridDim.x * blockDim.x) {
        int lane = t & 31, half = (t >> 5) & 1;
        int T = (t >> 6) % NT, S = t / (64 * NT);
        int row = lane >> 2, kc = lane & 3;
        int k = 8 * S + kc + 4 * half;
        int n = 8 * T + row;
        float v = 0.f;
        if (n < mcols)              v = Wm[k * ldm + n];
        else if (n < mcols + ecols) v = We[k * lde + (n - mcols)];
        dst[t] = tf32r(v);
    }
}

// ---------------- kernel A: node pre-linears (tf32 MMA, 32 nodes/block) ----
template <int OS, bool SCR>
__global__ void __launch_bounds__(256, 3) k_node_pre(
    const float* __restrict__ ns_in, const float* __restrict__ nv_in,
    const float* __restrict__ attr)
{
    constexpr int NB = 32, ST = 40;
    constexpr int NTs = (64 + OS) / 8;   // 20 or 16
    constexpr int TPW = NTs / 4;         // 5 or 4 tiles per warp
    constexpr int STO = 64 + OS + 4;     // 164 or 132
    constexpr int SVO = 196;

    extern __shared__ float sm[];
    float* s_nsT  = sm;                    // 64*40
    float* s_nvT  = s_nsT + 64 * ST;       // 96*40
    float* s_out  = s_nvT + 96 * ST;       // NB*STO
    float* s_vout = s_out + NB * STO;      // NB*196
    float* s_attr = s_vout + NB * SVO;     // 32

    const int t = threadIdx.x;
    const int nb0 = blockIdx.x * NB;
    const float* ns = SCR ? d_gs : ns_in;
    const float* nv = SCR ? d_v1 : nv_in;

    if (t < NB) s_attr[t] = (nb0 + t < N_NODES) ? attr[nb0 + t] : 0.f;
    for (int idx = t; idx < NB * 64; idx += 256) {
        int n = idx >> 6, u = idx & 63, ng = nb0 + n;
        float v = (ng < N_NODES) ? ns[ng * 64 + u] : 0.f;
        s_nsT[u * ST + n] = tf32r(v);
    }
    for (int idx = t; idx < NB * 96; idx += 256) {
        int n = idx / 96, f = idx % 96, ng = nb0 + n;
        int u = f / 3, i = f - 3 * u;
        float v = (ng < N_NODES) ? nv[ng * 96 + f] : 0.f;
        s_nvT[(i * 32 + u) * ST + n] = tf32r(v);
    }
    __syncthreads();

    const int lane = t & 31, wp = t >> 5;
    const int m0 = (wp & 1) * 16, g = wp >> 1;
    const int row = lane >> 2, kc = lane & 3;
    const float* tabS = d_preS[SCR ? 1 : 0];
    const float* tabV = d_preV[SCR ? 1 : 0];

    // ---- scalar GEMM: [32 x 64] @ [64 x (64+OS)] ----
    {
        float cs[TPW][4];
#pragma unroll
        for (int i = 0; i < TPW; ++i)
#pragma unroll
            for (int j = 0; j < 4; ++j) cs[i][j] = 0.f;
#pragma unroll
        for (int S = 0; S < 8; ++S) {
            int kk = S * 8;
            uint32_t a0 = __float_as_uint(s_nsT[(kk + kc)     * ST + m0 + row]);
            uint32_t a1 = __float_as_uint(s_nsT[(kk + kc)     * ST + m0 + row + 8]);
            uint32_t a2 = __float_as_uint(s_nsT[(kk + kc + 4) * ST + m0 + row]);
            uint32_t a3 = __float_as_uint(s_nsT[(kk + kc + 4) * ST + m0 + row + 8]);
#pragma unroll
            for (int tt = 0; tt < TPW; ++tt) {
                int T = g * TPW + tt;
                const float* bp = tabS + (S * NTs + T) * 64 + lane;
                uint32_t b0 = __float_as_uint(__ldg(bp));
                uint32_t b1 = __float_as_uint(__ldg(bp + 32));
                mma_tf32(cs[tt], a0, a1, a2, a3, b0, b1);
            }
        }
#pragma unroll
        for (int tt = 0; tt < TPW; ++tt) {
            int col = (g * TPW + tt) * 8 + kc * 2;
            int r0 = m0 + row;
            s_out[r0 * STO + col]           = cs[tt][0];
            s_out[r0 * STO + col + 1]       = cs[tt][1];
            s_out[(r0 + 8) * STO + col]     = cs[tt][2];
            s_out[(r0 + 8) * STO + col + 1] = cs[tt][3];
        }
    }
    // ---- vector GEMMs: 3 x ([32 x 32] @ [32 x 64]) ----
    {
        float cv[6][4];
#pragma unroll
        for (int i = 0; i < 6; ++i)
#pragma unroll
            for (int j = 0; j < 4; ++j) cv[i][j] = 0.f;
#pragma unroll
        for (int vtl = 0; vtl < 6; ++vtl) {
            int vt = g * 6 + vtl, i = vt >> 3, T = vt & 7;
#pragma unroll
            for (int S = 0; S < 4; ++S) {
                int kb = i * 32 + S * 8;
                uint32_t a0 = __float_as_uint(s_nvT[(kb + kc)     * ST + m0 + row]);
                uint32_t a1 = __float_as_uint(s_nvT[(kb + kc)     * ST + m0 + row + 8]);
                uint32_t a2 = __float_as_uint(s_nvT[(kb + kc + 4) * ST + m0 + row]);
                uint32_t a3 = __float_as_uint(s_nvT[(kb + kc + 4) * ST + m0 + row + 8]);
                const float* bp = tabV + (S * 8 + T) * 64 + lane;
                uint32_t b0 = __float_as_uint(__ldg(bp));
                uint32_t b1 = __float_as_uint(__ldg(bp + 32));
                mma_tf32(cv[vtl], a0, a1, a2, a3, b0, b1);
            }
        }
#pragma unroll
        for (int vtl = 0; vtl < 6; ++vtl) {
            int vt = g * 6 + vtl, i = vt >> 3, T = vt & 7;
            int col = T * 8 + kc * 2;
            int r0 = m0 + row;
            s_vout[r0 * SVO + i * 64 + col]           = cv[vtl][0];
            s_vout[r0 * SVO + i * 64 + col + 1]       = cv[vtl][1];
            s_vout[(r0 + 8) * SVO + i * 64 + col]     = cv[vtl][2];
            s_vout[(r0 + 8) * SVO + i * 64 + col + 1] = cv[vtl][3];
        }
    }
    __syncthreads();

    // ---- epilogue: scale + store + zero accumulators ----
    for (int idx = t; idx < NB * 64; idx += 256) {
        int n = idx >> 6, c = idx & 63, ng = nb0 + n;
        if (ng < N_NODES) d_hs[ng * 64 + c] = s_out[n * STO + c] * (s_attr[n] * INV_S64);
    }
    for (int idx = t; idx < NB * OS; idx += 256) {
        int n = idx / OS, c = idx % OS, ng = nb0 + n;
        if (ng < N_NODES) d_scs[ng * OS + c] = s_out[n * STO + 64 + c] * (s_attr[n] * INV_S64);
    }
    for (int idx = t; idx < NB * 96; idx += 256) {
        int n = idx / 96, f = idx % 96, ng = nb0 + n;
        int k = f / 3, i = f - 3 * k;
        if (ng < N_NODES) {
            float fv = s_attr[n] * INV_S32;
            d_hv [ng * 96 + f] = s_vout[n * SVO + i * 64 + k]      * fv;
            d_scv[ng * 96 + f] = s_vout[n * SVO + i * 64 + 32 + k] * fv;
        }
    }
    for (int idx = t; idx < NB * 24; idx += 256) {
        int n = idx / 24, j = idx % 24, ng = nb0 + n;
        if (ng < N_NODES) ((float4*)d_Ms)[ng * 24 + j] = make_float4(0.f, 0.f, 0.f, 0.f);
    }
    for (int idx = t; idx < NB * 72; idx += 256) {
        int n = idx / 72, j = idx % 72, ng = nb0 + n;
        if (ng < N_NODES) ((float4*)d_Mv)[ng * 72 + j] = make_float4(0.f, 0.f, 0.f, 0.f);
    }
}

// ---------------- kernel B: fused edge MLP (tf32 MMA) + messages + scatter -
#define SH_STRIDE 72
#define SW_STRIDE 196
#define B_SMEM_FLOATS (640 + 640 + 64*SH_STRIDE + 64*SW_STRIDE)  // 18432
#define B_SMEM_BYTES  (B_SMEM_FLOATS * 4)                        // 73728

__global__ void __launch_bounds__(256, 3) k_edge(
    const float* __restrict__ esc, const float* __restrict__ sh,
    const int* __restrict__ src,   const int* __restrict__ dst,
    const float* __restrict__ Wfc1, int layer)
{
    extern __shared__ float sm[];
    float* s_w1  = sm;
    float* s_esc = sm + 640;
    float* s_hT  = sm + 1280;
    float* s_w   = sm + 1280 + 64 * SH_STRIDE;

    const int t  = threadIdx.x;
    const int e0 = blockIdx.x * EPB;
    const int lane = t & 31, wp = t >> 5;

    for (int i = t; i < 640; i += 256) s_w1[i]  = Wfc1[i];
    for (int i = t; i < 640; i += 256) s_esc[i] = esc[e0 * 10 + i];
    __syncthreads();

    // ---- phase 1 ----
    {
        int e = t & 63, q = t >> 6;
        float es[10];
#pragma unroll
        for (int u = 0; u < 10; ++u) es[u] = s_esc[e * 10 + u];
#pragma unroll
        for (int c = 0; c < 16; ++c) {
            int col = q * 16 + c;
            float acc = 0.f;
#pragma unroll
            for (int u = 0; u < 10; ++u) acc += es[u] * s_w1[u * 64 + col];
            s_hT[col * SH_STRIDE + e] = tf32r(siluf_(acc * INV_S10));
        }
    }
    __syncthreads();

    // ---- phase 2 ----
    {
        const int m0   = (wp & 3) * 16;
        const int tb   = (wp >> 2) * 12;
        const int row  = lane >> 2, kc = lane & 3;
        const float* w2f = (const float*)d_w2f[layer];

        float c[12][4];
#pragma unroll
        for (int i = 0; i < 12; ++i)
#pragma unroll
            for (int j = 0; j < 4; ++j) c[i][j] = 0.f;

#pragma unroll
        for (int S = 0; S < 8; ++S) {
            int kk = S * 8;
            uint32_t a0 = __float_as_uint(s_hT[(kk + kc)     * SH_STRIDE + m0 + row]);
            uint32_t a1 = __float_as_uint(s_hT[(kk + kc)     * SH_STRIDE + m0 + row + 8]);
            uint32_t a2 = __float_as_uint(s_hT[(kk + kc + 4) * SH_STRIDE + m0 + row]);
            uint32_t a3 = __float_as_uint(s_hT[(kk + kc + 4) * SH_STRIDE + m0 + row + 8]);
#pragma unroll
            for (int tt = 0; tt < 12; ++tt) {
                int T = tb + tt;
                const float* bp = w2f + ((S * 24 + T) * 2) * 32 + lane;
                uint32_t b0 = __float_as_uint(__ldg(bp));
                uint32_t b1 = __float_as_uint(__ldg(bp + 32));
                mma_tf32(c[tt], a0, a1, a2, a3, b0, b1);
            }
        }
#pragma unroll
        for (int tt = 0; tt < 12; ++tt) {
            int col = (tb + tt) * 8 + kc * 2;
            int r0  = m0 + row;
            s_w[r0 * SW_STRIDE + col]           = c[tt][0] * INV_S64;
            s_w[r0 * SW_STRIDE + col + 1]       = c[tt][1] * INV_S64;
            s_w[(r0 + 8) * SW_STRIDE + col]     = c[tt][2] * INV_S64;
            s_w[(r0 + 8) * SW_STRIDE + col + 1] = c[tt][3] * INV_S64;
        }
    }
    __syncthreads();

    // ---- phase 3 ----
    {
#pragma unroll
        for (int ei = 0; ei < 8; ++ei) {
            int e  = wp * 8 + ei;
            int ge = e0 + e;
            int sn = __ldg(src + ge), dn = __ldg(dst + ge);
            float4 sh4 = __ldg((const float4*)(sh + ge * 4));
            float s0 = sh4.x, vx = sh4.y, vy = sh4.z, vz = sh4.w;
            const float* we  = s_w + e * SW_STRIDE;
            const float* hsp = d_hs + sn * 64;
            const float* hvp = d_hv + sn * 96;
            float* msd = d_Ms + dn * 96;
            float* mvd = d_Mv + dn * 288;

            if (lane < 16) {
                int j0 = lane * 4;
                float4 h4 = *(const float4*)(hsp + j0);
                float4 wa = *(const float4*)(we + j0);
                red4(msd + j0, make_float4(h4.x * s0 * wa.x, h4.y * s0 * wa.y,
                                           h4.z * s0 * wa.z, h4.w * s0 * wa.w));
            } else if (lane < 24) {
                int jp0 = (lane - 16) * 4;
                const float* gp = hvp + jp0 * 3;
                float4 ga = *(const float4*)gp;
                float4 gb = *(const float4*)(gp + 4);
                float4 gc = *(const float4*)(gp + 8);
                float4 w4 = *(const float4*)(we + 160 + jp0);
                float4 v;
                v.x = (ga.x * vx + ga.y * vy + ga.z * vz) * INV_S3 * w4.x;
                v.y = (ga.w * vx + gb.x * vy + gb.y * vz) * INV_S3 * w4.y;
                v.z = (gb.z * vx + gb.w * vy + gc.x * vz) * INV_S3 * w4.z;
                v.w = (gc.y * vx + gc.z * vy + gc.w * vz) * INV_S3 * w4.w;
                red4(msd + 64 + jp0, v);
            }
            {
                int f0 = lane * 4;
                float v[4];
#pragma unroll
                for (int c2 = 0; c2 < 4; ++c2) {
                    int f = f0 + c2, j = f / 3, i2 = f - 3 * j;
                    float shvi = (i2 == 0) ? vx : ((i2 == 1) ? vy : vz);
                    v[c2] = hsp[j] * shvi * we[64 + j];
                }
                red4(mvd + f0, make_float4(v[0], v[1], v[2], v[3]));
                if (lane < 16) {
                    int f1 = 128 + lane * 4;
                    float u2[4];
#pragma unroll
                    for (int c2 = 0; c2 < 4; ++c2) {
                        int f = f1 + c2, j = f / 3, i2 = f - 3 * j;
                        float shvi = (i2 == 0) ? vx : ((i2 == 1) ? vy : vz);
                        u2[c2] = hsp[j] * shvi * we[64 + j];
                    }
                    red4(mvd + f1, make_float4(u2[0], u2[1], u2[2], u2[3]));
                }
            }
            if (lane < 24) {
                int i0 = lane * 4;
                float4 g4 = *(const float4*)(hvp + i0);
                float4 v;
                v.x = g4.x * s0 * we[128 + (i0    ) / 3];
                v.y = g4.y * s0 * we[128 + (i0 + 1) / 3];
                v.z = g4.z * s0 * we[128 + (i0 + 2) / 3];
                v.w = g4.w * s0 * we[128 + (i0 + 3) / 3];
                red4(mvd + 192 + i0, v);
            }
        }
    }
}

// ---------------- kernel C: node finalize (tf32 MMA, 32 nodes/block) -------
template <int OS, bool L1F>
__global__ void __launch_bounds__(256, 2) k_node_post(
    const float* __restrict__ attr, float* __restrict__ out)
{
    constexpr int NB = 32, ST = 40;
    constexpr int NTp = (OS + 8) / 8;    // 13 (OS=96) or 9 (OS=64); Wa at col OS
    constexpr int STO = NTp * 8;         // 104 or 72 (both ≡ 8 mod 32)
    constexpr int SVO = 100;

    extern __shared__ float sm[];
    float* s_MsT  = sm;                    // 96*40
    float* s_MvT  = s_MsT + 96 * ST;       // 288*40
    float* s_out  = s_MvT + 288 * ST;      // NB*STO
    float* s_vout = s_out + NB * STO;      // NB*100
    float* s_attr = s_vout + NB * SVO;     // 32
    float* s_inv  = s_attr + NB;           // 32
    float* s_fac  = s_inv + NB;            // 32

    const int t = threadIdx.x;
    const int nb0 = blockIdx.x * NB;

    if (t < NB) {
        int ng = nb0 + t;
        s_attr[t] = (ng < N_NODES) ? attr[ng] : 0.f;
        s_inv[t]  = (ng < N_NODES) ? 1.0f / fmaxf(d_deg[ng], 1.0f) : 0.f;
    }
    for (int idx = t; idx < NB * 96; idx += 256) {
        int n = idx / 96, u = idx % 96, ng = nb0 + n;
        float v = (ng < N_NODES) ? d_Ms[ng * 96 + u] : 0.f;
        s_MsT[u * ST + n] = tf32r(v);
    }
    for (int idx = t; idx < NB * 288; idx += 256) {
        int n = idx / 288, f = idx % 288, ng = nb0 + n;
        int u = f / 3, i = f - 3 * u;
        float v = (ng < N_NODES) ? d_Mv[ng * 288 + f] : 0.f;
        s_MvT[(i * 96 + u) * ST + n] = tf32r(v);
    }
    __syncthreads();

    const int lane = t & 31, wp = t >> 5;
    const int m0 = (wp & 1) * 16, g = wp >> 1;
    const int row = lane >> 2, kc = lane & 3;
    const int lay = L1F ? 0 : 1;
    const float* tabS = d_postS[lay];
    const float* tabV = d_postV[lay];

    // ---- scalar GEMM: [32 x 96] @ [96 x (OS+1)] (Wa fused as last col) ----
    {
        const int base = NTp / 4, rem = NTp % 4;
        const int myN = base + (g < rem ? 1 : 0);
        const int myStart = g * base + (g < rem ? g : rem);
        float cs[4][4];
#pragma unroll
        for (int i = 0; i < 4; ++i)
#pragma unroll
            for (int j = 0; j < 4; ++j) cs[i][j] = 0.f;
#pragma unroll
        for (int S = 0; S < 12; ++S) {
            int kk = S * 8;
            uint32_t a0 = __float_as_uint(s_MsT[(kk + kc)     * ST + m0 + row]);
            uint32_t a1 = __float_as_uint(s_MsT[(kk + kc)     * ST + m0 + row + 8]);
            uint32_t a2 = __float_as_uint(s_MsT[(kk + kc + 4) * ST + m0 + row]);
            uint32_t a3 = __float_as_uint(s_MsT[(kk + kc + 4) * ST + m0 + row + 8]);
            for (int tt = 0; tt < myN; ++tt) {
                int T = myStart + tt;
                const float* bp = tabS + (S * NTp + T) * 64 + lane;
                uint32_t b0 = __float_as_uint(__ldg(bp));
                uint32_t b1 = __float_as_uint(__ldg(bp + 32));
                mma_tf32(cs[tt], a0, a1, a2, a3, b0, b1);
            }
        }
        for (int tt = 0; tt < myN; ++tt) {
            int col = (myStart + tt) * 8 + kc * 2;
            int r0 = m0 + row;
            s_out[r0 * STO + col]           = cs[tt][0];
            s_out[r0 * STO + col + 1]       = cs[tt][1];
            s_out[(r0 + 8) * STO + col]     = cs[tt][2];
            s_out[(r0 + 8) * STO + col + 1] = cs[tt][3];
        }
    }
    // ---- vector GEMMs: 3 x ([32 x 96] @ [96 x 32]) ----
    {
        float cv[3][4];
#pragma unroll
        for (int i = 0; i < 3; ++i)
#pragma unroll
            for (int j = 0; j < 4; ++j) cv[i][j] = 0.f;
#pragma unroll
        for (int v = 0; v < 3; ++v) {
            int vti = g * 3 + v, i = vti >> 2, T = vti & 3;
#pragma unroll
            for (int S = 0; S < 12; ++S) {
                int kb = i * 96 + S * 8;
                uint32_t a0 = __float_as_uint(s_MvT[(kb + kc)     * ST + m0 + row]);
                uint32_t a1 = __float_as_uint(s_MvT[(kb + kc)     * ST + m0 + row + 8]);
                uint32_t a2 = __float_as_uint(s_MvT[(kb + kc + 4) * ST + m0 + row]);
                uint32_t a3 = __float_as_uint(s_MvT[(kb + kc + 4) * ST + m0 + row + 8]);
                const float* bp = tabV + (S * 4 + T) * 64 + lane;
                uint32_t b0 = __float_as_uint(__ldg(bp));
                uint32_t b1 = __float_as_uint(__ldg(bp + 32));
                mma_tf32(cv[v], a0, a1, a2, a3, b0, b1);
            }
        }
#pragma unroll
        for (int v = 0; v < 3; ++v) {
            int vti = g * 3 + v, i = vti >> 2, T = vti & 3;
            int col = T * 8 + kc * 2;
            int r0 = m0 + row;
            s_vout[r0 * SVO + i * 32 + col]           = cv[v][0];
            s_vout[r0 * SVO + i * 32 + col + 1]       = cv[v][1];
            s_vout[(r0 + 8) * SVO + i * 32 + col]     = cv[v][2];
            s_vout[(r0 + 8) * SVO + i * 32 + col + 1] = cv[v][3];
        }
    }
    __syncthreads();

    if (t < NB) {
        float alpha = s_out[t * STO + OS] * s_inv[t] * INV_S96 * s_attr[t];
        s_fac[t] = alpha * s_inv[t] * s_attr[t] * INV_S96;
    }
    __syncthreads();

    // ---- epilogue ----
    if (L1F) {
        for (int idx = t; idx < NB * 64; idx += 256) {
            int n = idx >> 6, c = idx & 63, ng = nb0 + n;
            if (ng < N_NODES) {
                float val = d_scs[ng * 96 + c] + s_out[n * STO + c] * s_fac[n];
                d_gs[ng * 64 + c] = siluf_(val);
            }
        }
        for (int idx = t; idx < NB * 32; idx += 256) {
            int n = idx >> 5, k = idx & 31, ng = nb0 + n;
            if (ng < N_NODES) {
                float sC = d_scs[ng * 96 + 64 + k] + s_out[n * STO + 64 + k] * s_fac[n];
                float sg = sigmoidf_(sC);
#pragma unroll
                for (int i = 0; i < 3; ++i) {
                    float v = d_scv[ng * 96 + k * 3 + i]
                            + s_vout[n * SVO + i * 32 + k] * s_fac[n];
                    d_v1[ng * 96 + k * 3 + i] = v * sg;
                }
            }
        }
    } else {
        for (int idx = t; idx < NB * 64; idx += 256) {
            int n = idx >> 6, c = idx & 63, ng = nb0 + n;
            if (ng < N_NODES)
                out[ng * 160 + c] = d_scs[ng * 64 + c] + s_out[n * STO + c] * s_fac[n];
        }
        for (int idx = t; idx < NB * 96; idx += 256) {
            int n = idx / 96, f = idx % 96, ng = nb0 + n;
            int k = f / 3, i = f - 3 * k;
            if (ng < N_NODES)
                out[ng * 160 + 64 + f] = d_scv[ng * 96 + f]
                                       + s_vout[n * SVO + i * 32 + k] * s_fac[n];
        }
    }
}

// ---------------- launch ----------------------------------------------------
extern "C" void kernel_launch(void* const* d_in, const int* in_sizes, int n_in,
                              void* d_out, int out_size)
{
    const float* node_s = (const float*)d_in[0];
    const float* node_v = (const float*)d_in[1];
    const float* attr   = (const float*)d_in[2];
    const int*   src    = (const int*)d_in[3];
    const int*   dst    = (const int*)d_in[4];
    const float* sh     = (const float*)d_in[5];
    const float* esc    = (const float*)d_in[6];
    const float* w1[9];
    const float* w2[9];
    for (int i = 0; i < 9; ++i) { w1[i] = (const float*)d_in[7 + i]; w2[i] = (const float*)d_in[16 + i]; }
    float* out = (float*)d_out;

    // dynamic smem sizes (floats -> bytes)
    const int preSM96  = (64*40 + 96*40 + 32*164 + 32*196 + 32) * 4;   // 71808
    const int preSM64  = (64*40 + 96*40 + 32*132 + 32*196 + 32) * 4;   // 67712
    const int postSM96 = (96*40 + 288*40 + 32*104 + 32*100 + 96) * 4;  // 87936
    const int postSM64 = (96*40 + 288*40 + 32*72  + 32*100 + 96) * 4;  // 83840

    cudaFuncSetAttribute(k_edge, cudaFuncAttributeMaxDynamicSharedMemorySize, B_SMEM_BYTES);
    cudaFuncSetAttribute(k_node_pre<96, false>, cudaFuncAttributeMaxDynamicSharedMemorySize, preSM96);
    cudaFuncSetAttribute(k_node_pre<64, true>,  cudaFuncAttributeMaxDynamicSharedMemorySize, preSM64);
    cudaFuncSetAttribute(k_node_post<96, true>, cudaFuncAttributeMaxDynamicSharedMemorySize, postSM96);
    cudaFuncSetAttribute(k_node_post<64, false>,cudaFuncAttributeMaxDynamicSharedMemorySize, postSM64);

    const int nodeBlocks = (N_NODES + 31) / 32;   // 1563

    k_deg_zero<<<(N_NODES + 255) / 256, 256>>>();
    k_deg<<<(N_EDGES + 255) / 256, 256>>>(dst);
    k_prep<<<96, 256>>>(w1[5], w2[5]);
    // pre tables: lin1_s || sc_s (K=64), lin1_v || sc_v (K=32)
    k_pack<<<40, 256>>>(0, 0, w1[2], w1[0], 64, 20, 64, 64, 96, 96);
    k_pack<<<32, 256>>>(0, 1, w2[2], w2[0], 64, 16, 64, 64, 64, 64);
    k_pack<<<8, 256>>> (1, 0, w1[3], w1[1], 32, 8, 32, 32, 32, 32);
    k_pack<<<8, 256>>> (1, 1, w2[3], w2[1], 32, 8, 32, 32, 32, 32);
    // post tables: lin2_s || alpha (K=96), lin2_v (K=96)
    k_pack<<<39, 256>>>(2, 0, w1[6], w1[8], 96, 13, 96, 96, 1, 1);
    k_pack<<<27, 256>>>(2, 1, w2[6], w2[8], 96, 9, 64, 64, 1, 1);
    k_pack<<<12, 256>>>(3, 0, w1[7], w1[7], 96, 4, 32, 32, 0, 0);
    k_pack<<<12, 256>>>(3, 1, w2[7], w2[7], 96, 4, 32, 32, 0, 0);

    // ---- layer 1 (o_s = 96) ----
    k_node_pre<96, false><<<nodeBlocks, 256, preSM96>>>(node_s, node_v, attr);
    k_edge<<<N_EDGES / EPB, 256, B_SMEM_BYTES>>>(esc, sh, src, dst, w1[4], 0);
    k_node_post<96, true><<<nodeBlocks, 256, postSM96>>>(attr, out);

    // ---- layer 2 (o_s = 64) ----
    k_node_pre<64, true><<<nodeBlocks, 256, preSM64>>>(nullptr, nullptr, attr);
    k_edge<<<N_EDGES / EPB, 256, B_SMEM_BYTES>>>(esc, sh, src, dst, w2[4], 1);
    k_node_post<64, false><<<nodeBlocks, 256, postSM64>>>(attr, out);

    (void)in_sizes; (void)n_in; (void)out_size;
}